// round 9
// baseline (speedup 1.0000x reference)
#include <cuda_runtime.h>
#include <cuda_bf16.h>
#include <math.h>
#include <stdint.h>

// Problem constants
#define BB 2
#define TS 2048
#define HH 16
#define DD 128
#define CC 2048
#define MMR (BB*TS)
#define KPA 4096             // compact split stride: [hi | lo]
#define NCHUNK 96            // logical K' = 3*2048 in 96 chunks of 64

// 1/sqrt(2048)
#define RSQT 0.022097086912079608f

// ---------------------------------------------------------------------------
// Device scratch
// ---------------------------------------------------------------------------
__device__ float g_V [(size_t)BB*HH*TS*DD];          // fp32 V [bh][t][d]
__device__ float g_cfac[TS*DD];
__device__ int   g_ctr[4];
__device__ __nv_bfloat16 g_Qh[(size_t)BB*HH*TS*DD];  // [bh][t][d]
__device__ __nv_bfloat16 g_Ql[(size_t)BB*HH*TS*DD];
__device__ __nv_bfloat16 g_Kh[(size_t)BB*HH*TS*DD];
__device__ __nv_bfloat16 g_Kl[(size_t)BB*HH*TS*DD];
__device__ __nv_bfloat16 g_Vth[(size_t)BB*HH*TS*DD]; // V^T hi [bh][d][t]
__device__ __nv_bfloat16 g_Vtl[(size_t)BB*HH*TS*DD]; // V^T lo
__device__ __nv_bfloat16 g_Xs [(size_t)MMR*KPA];     // [m][4096] : [Xh | Xl]
__device__ __nv_bfloat16 g_AOs[(size_t)MMR*KPA];     // [m][4096] : [AOh | AOl]
__device__ __nv_bfloat16 g_Wt [(size_t)4*CC*KPA];    // [w][n][4096] : [Wh | Wl]

// ---------------------------------------------------------------------------
// PTX helpers (sm_100-baseline-safe)
// ---------------------------------------------------------------------------
__device__ __forceinline__ uint32_t smem_u32(const void* p) {
    uint32_t a;
    asm("{ .reg .u64 t; cvta.to.shared.u64 t, %1; cvt.u32.u64 %0, t; }" : "=r"(a) : "l"(p));
    return a;
}
__device__ __forceinline__ void ldsm4(uint32_t* r, uint32_t addr) {
    asm volatile("ldmatrix.sync.aligned.m8n8.x4.shared.b16 {%0,%1,%2,%3}, [%4];"
        : "=r"(r[0]), "=r"(r[1]), "=r"(r[2]), "=r"(r[3]) : "r"(addr));
}
__device__ __forceinline__ void mma16816(float* d, const uint32_t* a, const uint32_t* b) {
    asm volatile("mma.sync.aligned.m16n8k16.row.col.f32.bf16.bf16.f32 "
        "{%0,%1,%2,%3}, {%4,%5,%6,%7}, {%8,%9}, {%0,%1,%2,%3};"
        : "+f"(d[0]), "+f"(d[1]), "+f"(d[2]), "+f"(d[3])
        : "r"(a[0]), "r"(a[1]), "r"(a[2]), "r"(a[3]), "r"(b[0]), "r"(b[1]));
}
__device__ __forceinline__ void cpa16(uint32_t s, const void* g) {
    asm volatile("cp.async.cg.shared.global [%0], [%1], 16;" :: "r"(s), "l"(g));
}
#define CP_COMMIT() asm volatile("cp.async.commit_group;")
#define CP_WAIT(n)  asm volatile("cp.async.wait_group %0;" :: "n"(n))

__device__ __forceinline__ uint32_t bf2u(__nv_bfloat16 a, __nv_bfloat16 b) {
    __nv_bfloat162 t = __halves2bfloat162(a, b);
    return *(uint32_t*)&t;
}
// swizzled smem address, 256B rows
#define ASW(base, r, kb) ((base) + (uint32_t)(r) * 256 + (((uint32_t)(kb)) ^ ((((uint32_t)(r)) & 7) << 4)))
// swizzled smem address, 128B rows (packed V^T tile)
#define AVW(base, r, kb) ((base) + (uint32_t)(r) * 128 + (((uint32_t)(kb)) ^ ((((uint32_t)(r)) & 7) << 4)))

// ---------------------------------------------------------------------------
// tiny kernels
// ---------------------------------------------------------------------------
__global__ void reset_ctr_kernel() {
    if (threadIdx.x < 4) g_ctr[threadIdx.x] = 0;
}

__global__ void cfac_kernel() {
    int t = blockIdx.x;
    int d = threadIdx.x;
    int j = d & 63;
    float ex = (float)(2 * j) / 128.0f;
    float freq = 1.0f / powf(10000.0f, ex);
    float m = (float)t * freq;
    g_cfac[t * DD + d] = cosf(m) + sinf(m);
}

__global__ __launch_bounds__(256) void split_kernel(const float* __restrict__ xin) {
    int idx = blockIdx.x * 256 + threadIdx.x;
    int m = idx >> 9;
    int kv = (idx & 511) << 2;
    float4 x = *(const float4*)(xin + (size_t)m * CC + kv);
    __nv_bfloat16 h0 = __float2bfloat16_rn(x.x);
    __nv_bfloat16 h1 = __float2bfloat16_rn(x.y);
    __nv_bfloat16 h2 = __float2bfloat16_rn(x.z);
    __nv_bfloat16 h3 = __float2bfloat16_rn(x.w);
    __nv_bfloat16 l0 = __float2bfloat16_rn(x.x - __bfloat162float(h0));
    __nv_bfloat16 l1 = __float2bfloat16_rn(x.y - __bfloat162float(h1));
    __nv_bfloat16 l2 = __float2bfloat16_rn(x.z - __bfloat162float(h2));
    __nv_bfloat16 l3 = __float2bfloat16_rn(x.w - __bfloat162float(h3));
    __nv_bfloat16* p = g_Xs + (size_t)m * KPA + kv;
    *(__nv_bfloat162*)(p)        = __halves2bfloat162(h0, h1);
    *(__nv_bfloat162*)(p + 2)    = __halves2bfloat162(h2, h3);
    *(__nv_bfloat162*)(p + 2048) = __halves2bfloat162(l0, l1);
    *(__nv_bfloat162*)(p + 2050) = __halves2bfloat162(l2, l3);
}

__global__ __launch_bounds__(256) void splitW_kernel(
    const float* __restrict__ Wq, const float* __restrict__ Wk,
    const float* __restrict__ Wv, const float* __restrict__ Wo)
{
    __shared__ float tile[32][33];
    int w = blockIdx.z;
    const float* W = (w == 0) ? Wq : (w == 1) ? Wk : (w == 2) ? Wv : Wo;
    __nv_bfloat16* out = g_Wt + (size_t)w * CC * KPA;
    int n0 = blockIdx.x * 32, k0 = blockIdx.y * 32;
    int tx = threadIdx.x & 31, ty = threadIdx.x >> 5;
#pragma unroll
    for (int r = 0; r < 4; r++) {
        int k = k0 + ty + r * 8;
        tile[ty + r * 8][tx] = W[(size_t)k * CC + n0 + tx];
    }
    __syncthreads();
#pragma unroll
    for (int r = 0; r < 4; r++) {
        int n = n0 + ty + r * 8;
        int k = k0 + tx;
        float x = tile[tx][ty + r * 8];
        __nv_bfloat16 hi = __float2bfloat16_rn(x);
        __nv_bfloat16 lo = __float2bfloat16_rn(x - __bfloat162float(hi));
        __nv_bfloat16* pr = out + (size_t)n * KPA;
        pr[k] = hi; pr[2048 + k] = lo;
    }
}

__global__ __launch_bounds__(256) void vtrans_kernel() {
    __shared__ float tile[32][33];
    int bh = blockIdx.z, t0 = blockIdx.x * 32, d0 = blockIdx.y * 32;
    int tx = threadIdx.x & 31, ty = threadIdx.x >> 5;
    const float* src = g_V + (size_t)bh * TS * DD;
#pragma unroll
    for (int r = 0; r < 4; r++)
        tile[ty + r * 8][tx] = src[(size_t)(t0 + ty + r * 8) * DD + d0 + tx];
    __syncthreads();
#pragma unroll
    for (int r = 0; r < 4; r++) {
        int d = d0 + ty + r * 8;
        int t = t0 + tx;
        float v = tile[tx][ty + r * 8];
        __nv_bfloat16 hv = __float2bfloat16_rn(v);
        __nv_bfloat16 lv = __float2bfloat16_rn(v - __bfloat162float(hv));
        size_t off = (size_t)bh * DD * TS + (size_t)d * TS + t;
        g_Vth[off] = hv;
        g_Vtl[off] = lv;
    }
}

// ---------------------------------------------------------------------------
// mma.sync bf16 GEMM, 3-stage cp.async pipeline, 2 CTAs/SM, work-stealing.
// ---------------------------------------------------------------------------
#define SM_STAGE 32768
#define GEMM_SMEM (1024 + 3 * SM_STAGE)

__global__ __launch_bounds__(256, 2) void tc_gemm_kernel(int modeBase, int ntiles,
                                                         int ci, float* __restrict__ Cout)
{
    extern __shared__ char smc[];
    uint32_t sb = smem_u32(smc) + 1024;
    const int tid = threadIdx.x, wid = tid >> 5, lane = tid & 31;
    const int wm = wid >> 1, wn = wid & 1;

    const int ldrow = tid >> 3;
    const int ldc16 = tid & 7;
    const uint32_t sw = ((uint32_t)(ldrow * 128 + ldc16 * 16)) ^ ((ldrow & 7) << 4);

    const int lh16 = (lane >> 4) * 16;
    const int rowA0 = wm * 32 + (lane & 15);
    const int kbB = ((lane >> 3) & 1) * 16;
    const int rbase = wn * 64 + ((lane >> 4) << 3) + (lane & 7);
    const int rsub = lane >> 2, cb = (lane & 3) * 2;

#define AOFF(k0) ((k0) < 2048 ? (k0) : (k0) - 2048)
#define BOFF(k0) ((k0) < 4096 ? (k0) : (k0) - 4096)

    for (;;) {
        __syncthreads();
        if (tid == 0) ((int*)smc)[0] = atomicAdd(&g_ctr[ci], 1);
        __syncthreads();
        int t = ((int*)smc)[0];
        if (t >= ntiles) { CP_WAIT(0); break; }
        const int mode = modeBase + (t >> 9);
        const int r_ = t & 511;
        const int bm = r_ >> 4, bn = r_ & 15;
        const __nv_bfloat16* A  = (mode == 3) ? g_AOs : g_Xs;
        const __nv_bfloat16* Bp = g_Wt + (size_t)mode * CC * KPA;
        const __nv_bfloat16* Arow = A  + (size_t)(bm * 128) * KPA;
        const __nv_bfloat16* Brow = Bp + (size_t)(bn * 128) * KPA;

        float c[2][8][4];
#pragma unroll
        for (int i = 0; i < 2; i++)
#pragma unroll
            for (int j = 0; j < 8; j++)
#pragma unroll
                for (int q = 0; q < 4; q++) c[i][j][q] = 0.0f;

        // prologue: chunks 0,1 -> stages 0,1
#pragma unroll
        for (int p = 0; p < 2; p++) {
            int k0 = p * 64;
            int ao = AOFF(k0), bo = BOFF(k0);
            uint32_t st = sb + p * SM_STAGE;
#pragma unroll
            for (int it = 0; it < 4; it++) {
                int row = ldrow + it * 32;
                cpa16(st + sw + it * 4096,         Arow + (size_t)row * KPA + ao + ldc16 * 8);
                cpa16(st + 16384 + sw + it * 4096, Brow + (size_t)row * KPA + bo + ldc16 * 8);
            }
            CP_COMMIT();
        }

        int stage = 0;
        for (int ch = 0; ch < NCHUNK; ch++) {
            CP_WAIT(1);
            __syncthreads();
            if (ch + 2 < NCHUNK) {
                int k0 = (ch + 2) * 64;
                int ao = AOFF(k0), bo = BOFF(k0);
                int ns = stage + 2; if (ns >= 3) ns -= 3;
                uint32_t st = sb + ns * SM_STAGE;
#pragma unroll
                for (int it = 0; it < 4; it++) {
                    int row = ldrow + it * 32;
                    cpa16(st + sw + it * 4096,         Arow + (size_t)row * KPA + ao + ldc16 * 8);
                    cpa16(st + 16384 + sw + it * 4096, Brow + (size_t)row * KPA + bo + ldc16 * 8);
                }
            }
            CP_COMMIT();

            uint32_t sbA = sb + stage * SM_STAGE;
            uint32_t sbB = sbA + 16384;
#pragma unroll
            for (int ks = 0; ks < 4; ks++) {
                uint32_t a[2][4], b[4][4];
#pragma unroll
                for (int i = 0; i < 2; i++) {
                    int row = rowA0 + i * 16;
                    uint32_t kb = ks * 32 + lh16;
                    ldsm4(a[i], sbA + row * 128 + (kb ^ ((row & 7) << 4)));
                }
#pragma unroll
                for (int g = 0; g < 4; g++) {
                    int row = rbase + g * 16;
                    uint32_t kb = ks * 32 + kbB;
                    ldsm4(b[g], sbB + row * 128 + (kb ^ ((row & 7) << 4)));
                }
#pragma unroll
                for (int i = 0; i < 2; i++)
#pragma unroll
                    for (int j = 0; j < 8; j++)
                        mma16816(c[i][j], a[i], &b[j >> 1][(j & 1) * 2]);
            }
            if (++stage == 3) stage = 0;
        }

        // epilogue
        const int m0g = bm * 128 + wm * 32;
        const int n0g = bn * 128 + wn * 64;
#pragma unroll
        for (int i = 0; i < 2; i++) {
#pragma unroll
            for (int half = 0; half < 2; half++) {
                int row = m0g + i * 16 + rsub + half * 8;
                if (mode == 3) {
                    float* drow = Cout + (size_t)row * CC;
#pragma unroll
                    for (int j = 0; j < 8; j++) {
                        int col = n0g + j * 8 + cb;
                        *(float2*)(drow + col) = make_float2(c[i][j][half * 2],
                                                             c[i][j][half * 2 + 1]);
                    }
                } else if (mode == 2) {
                    int b = row >> 11, tt = row & 2047;
#pragma unroll
                    for (int j = 0; j < 8; j++) {
                        int col = n0g + j * 8 + cb;
                        int h = col >> 7, d0 = col & 127;
                        float* dst = g_V + ((size_t)(b * HH + h) * TS + tt) * DD + d0;
                        *(float2*)dst = make_float2(c[i][j][half * 2], c[i][j][half * 2 + 1]);
                    }
                } else {
                    int b = row >> 11, tt = row & 2047;
                    __nv_bfloat16* outH = (mode == 0) ? g_Qh : g_Kh;
                    __nv_bfloat16* outL = (mode == 0) ? g_Ql : g_Kl;
                    float s = (mode == 0) ? RSQT : 1.0f;
#pragma unroll
                    for (int j = 0; j < 8; j++) {
                        int col = n0g + j * 8 + cb;
                        int h = col >> 7, d0 = col & 127;
                        float2 f = *(const float2*)(g_cfac + tt * DD + d0);
                        float v0 = c[i][j][half * 2]     * f.x * s;
                        float v1 = c[i][j][half * 2 + 1] * f.y * s;
                        __nv_bfloat16 h0 = __float2bfloat16_rn(v0);
                        __nv_bfloat16 h1 = __float2bfloat16_rn(v1);
                        __nv_bfloat16 l0 = __float2bfloat16_rn(v0 - __bfloat162float(h0));
                        __nv_bfloat16 l1 = __float2bfloat16_rn(v1 - __bfloat162float(h1));
                        size_t off = ((size_t)(b * HH + h) * TS + tt) * DD + d0;
                        *(uint32_t*)(outH + off) = bf2u(h0, h1);
                        *(uint32_t*)(outL + off) = bf2u(l0, l1);
                    }
                }
            }
        }
    }
}

// ---------------------------------------------------------------------------
// Tensor-core flash attention, split-bf16 (3-term), K-tile 32, 2 CTAs/SM,
// work-stealing over (bh, mblk) tiles. K double-buffered, V^T packed hi|lo.
// smem: ctrl | QH QL (64KB) | K 2 stages x (hi 8K + lo 8K) | V packed 16KB
// ---------------------------------------------------------------------------
#define AQ_H 1024
#define AQ_L (AQ_H + 32768)
#define AK_BASE (AQ_L + 32768)
#define AK_STAGE 16384
#define AV_BASE (AK_BASE + 2 * AK_STAGE)
#define ATT_SMEM (AV_BASE + 16384)

__global__ __launch_bounds__(256, 2) void attn_kernel(const float* __restrict__ mask)
{
    extern __shared__ char smc[];
    uint32_t sb = smem_u32(smc);
    const int tid = threadIdx.x, wid = tid >> 5, lane = tid & 31;
    const int rsub = lane >> 2, cb = (lane & 3) * 2;
    const int kbB = ((lane >> 3) & 1) * 16;
    const int rbB = (lane & 7) + ((lane >> 4) << 3);
    const int raA = wid * 16 + (lane & 15);
    const uint32_t kbA = (lane >> 4) * 16;

    for (;;) {
        __syncthreads();
        if (tid == 0) ((int*)smc)[0] = atomicAdd(&g_ctr[2], 1);
        __syncthreads();
        int tile = ((int*)smc)[0];
        if (tile >= 512) { CP_WAIT(0); break; }
        const int bh = tile >> 4, mblk = tile & 15;
        const int b = bh >> 4, h = bh & 15;
        const size_t qoff = (size_t)bh * TS * DD + (size_t)mblk * 128 * DD;
        const size_t koff = (size_t)bh * TS * DD;
        const size_t voff = (size_t)bh * DD * TS;
        const int q0 = mblk * 128 + wid * 16 + rsub;

        // Q hi/lo resident load
#pragma unroll
        for (int it = 0; it < 8; it++) {
            int id = it * 256 + tid;
            int r = id >> 4;
            uint32_t kb = (id & 15) * 16;
            cpa16(ASW(sb + AQ_H, r, kb), (const char*)g_Qh + ((qoff + (size_t)r * DD) << 1) + kb);
            cpa16(ASW(sb + AQ_L, r, kb), (const char*)g_Ql + ((qoff + (size_t)r * DD) << 1) + kb);
        }
        CP_COMMIT();
        // K tile 0 -> stage 0
#pragma unroll
        for (int it = 0; it < 4; it++) {
            int id = it * 256 + tid;
            int r = id >> 5, cc = (id >> 1) & 15, pl = id & 1;
            const char* src = (const char*)(pl ? g_Kl : g_Kh) + ((koff + (size_t)r * DD) << 1) + cc * 16;
            cpa16(ASW(sb + AK_BASE + pl * 8192, r, cc * 16), src);
        }
        CP_COMMIT();

        float mr0 = -1e30f, mr1 = -1e30f, lr0 = 0.0f, lr1 = 0.0f;
        float o[16][4];
#pragma unroll
        for (int j = 0; j < 16; j++)
#pragma unroll
            for (int q = 0; q < 4; q++) o[j][q] = 0.0f;

        for (int kt = 0; kt < 64; kt++) {
            __syncthreads();   // bar1: S(kt-1)/PV(kt-1) readers done
            // V(kt) -> packed V buf
#pragma unroll
            for (int it = 0; it < 4; it++) {
                int id = it * 256 + tid;
                int r = id >> 3, cc = (id >> 1) & 3, pl = id & 1;
                const char* src = (const char*)(pl ? g_Vtl : g_Vth)
                    + ((voff + (size_t)r * TS + kt * 32) << 1) + cc * 16;
                cpa16(AVW(sb + AV_BASE, r, pl * 64 + cc * 16), src);
            }
            CP_COMMIT();
            // K(kt+1) -> other stage
            if (kt + 1 < 64) {
                uint32_t ksb = sb + AK_BASE + ((kt + 1) & 1) * AK_STAGE;
#pragma unroll
                for (int it = 0; it < 4; it++) {
                    int id = it * 256 + tid;
                    int r = id >> 5, cc = (id >> 1) & 15, pl = id & 1;
                    const char* src = (const char*)(pl ? g_Kl : g_Kh)
                        + ((koff + (size_t)((kt + 1) * 32 + r) * DD) << 1) + cc * 16;
                    cpa16(ASW(ksb + pl * 8192, r, cc * 16), src);
                }
            }
            CP_COMMIT();
            CP_WAIT(2);        // K(kt) (and Q on kt==0) complete
            __syncthreads();   // bar2: visibility

            uint32_t KHs = sb + AK_BASE + (kt & 1) * AK_STAGE;
            uint32_t KLs = KHs + 8192;

            // ---- S = Qh*Kh + Qh*Kl + Ql*Kh (16q x 32k per warp) ----
            float s[4][4];
#pragma unroll
            for (int j = 0; j < 4; j++)
#pragma unroll
                for (int q = 0; q < 4; q++) s[j][q] = 0.0f;

#pragma unroll
            for (int ks = 0; ks < 8; ks++) {
                uint32_t aH[4], aL[4], bH[2][4], bL[2][4];
                uint32_t kba = ks * 32 + kbA;
                ldsm4(aH, ASW(sb + AQ_H, raA, kba));
                ldsm4(aL, ASW(sb + AQ_L, raA, kba));
#pragma unroll
                for (int g = 0; g < 2; g++) {
                    int rb = g * 16 + rbB;
                    uint32_t kb = ks * 32 + kbB;
                    ldsm4(bH[g], ASW(KHs, rb, kb));
                    ldsm4(bL[g], ASW(KLs, rb, kb));
                }
#pragma unroll
                for (int j = 0; j < 4; j++) {
                    mma16816(s[j], aH, &bH[j >> 1][(j & 1) * 2]);
                    mma16816(s[j], aH, &bL[j >> 1][(j & 1) * 2]);
                    mma16816(s[j], aL, &bH[j >> 1][(j & 1) * 2]);
                }
            }

            // ---- mask add ----
            const float* mrow0 = mask + ((size_t)b * TS + q0) * TS + (size_t)kt * 32;
            const float* mrow1 = mrow0 + (size_t)8 * TS;
#pragma unroll
            for (int j = 0; j < 4; j++) {
                float2 m0 = *(const float2*)(mrow0 + j * 8 + cb);
                float2 m1 = *(const float2*)(mrow1 + j * 8 + cb);
                s[j][0] += m0.x; s[j][1] += m0.y;
                s[j][2] += m1.x; s[j][3] += m1.y;
            }

            // ---- online softmax ----
            float mt0 = -1e30f, mt1 = -1e30f;
#pragma unroll
            for (int j = 0; j < 4; j++) {
                mt0 = fmaxf(mt0, fmaxf(s[j][0], s[j][1]));
                mt1 = fmaxf(mt1, fmaxf(s[j][2], s[j][3]));
            }
            mt0 = fmaxf(mt0, __shfl_xor_sync(0xffffffffu, mt0, 1));
            mt0 = fmaxf(mt0, __shfl_xor_sync(0xffffffffu, mt0, 2));
            mt1 = fmaxf(mt1, __shfl_xor_sync(0xffffffffu, mt1, 1));
            mt1 = fmaxf(mt1, __shfl_xor_sync(0xffffffffu, mt1, 2));
            float mn0 = fmaxf(mr0, mt0), mn1 = fmaxf(mr1, mt1);
            float al0 = __expf(mr0 - mn0), al1 = __expf(mr1 - mn1);
            mr0 = mn0; mr1 = mn1;
            float rs0 = 0.0f, rs1 = 0.0f;
#pragma unroll
            for (int j = 0; j < 4; j++) {
                s[j][0] = __expf(s[j][0] - mn0); rs0 += s[j][0];
                s[j][1] = __expf(s[j][1] - mn0); rs0 += s[j][1];
                s[j][2] = __expf(s[j][2] - mn1); rs1 += s[j][2];
                s[j][3] = __expf(s[j][3] - mn1); rs1 += s[j][3];
            }
            rs0 += __shfl_xor_sync(0xffffffffu, rs0, 1);
            rs0 += __shfl_xor_sync(0xffffffffu, rs0, 2);
            rs1 += __shfl_xor_sync(0xffffffffu, rs1, 1);
            rs1 += __shfl_xor_sync(0xffffffffu, rs1, 2);
            lr0 = lr0 * al0 + rs0;
            lr1 = lr1 * al1 + rs1;
#pragma unroll
            for (int j = 0; j < 16; j++) {
                o[j][0] *= al0; o[j][1] *= al0;
                o[j][2] *= al1; o[j][3] *= al1;
            }

            CP_WAIT(1);        // V(kt) complete
            __syncthreads();   // bar3: V visibility

            // ---- build P frags (hi/lo) from s ----
            uint32_t pH[2][4], pL[2][4];
#pragma unroll
            for (int ks2 = 0; ks2 < 2; ks2++) {
#pragma unroll
                for (int half = 0; half < 2; half++) {
                    int j = ks2 * 2 + half;
                    __nv_bfloat16 h0 = __float2bfloat16_rn(s[j][0]);
                    __nv_bfloat16 h1 = __float2bfloat16_rn(s[j][1]);
                    __nv_bfloat16 h2 = __float2bfloat16_rn(s[j][2]);
                    __nv_bfloat16 h3 = __float2bfloat16_rn(s[j][3]);
                    pH[ks2][half * 2 + 0] = bf2u(h0, h1);
                    pH[ks2][half * 2 + 1] = bf2u(h2, h3);
                    pL[ks2][half * 2 + 0] = bf2u(
                        __float2bfloat16_rn(s[j][0] - __bfloat162float(h0)),
                        __float2bfloat16_rn(s[j][1] - __bfloat162float(h1)));
                    pL[ks2][half * 2 + 1] = bf2u(
                        __float2bfloat16_rn(s[j][2] - __bfloat162float(h2)),
                        __float2bfloat16_rn(s[j][3] - __bfloat162float(h3)));
                }
            }

            // ---- O += Ph*Vh + Ph*Vl + Pl*Vh ----
#pragma unroll
            for (int ks2 = 0; ks2 < 2; ks2++) {
#pragma unroll
                for (int gp = 0; gp < 4; gp++) {
                    uint32_t bH2[2][4], bL2[2][4];
#pragma unroll
                    for (int e = 0; e < 2; e++) {
                        int rb = (gp * 2 + e) * 16 + rbB;
                        uint32_t khi = ks2 * 32 + kbB;
                        ldsm4(bH2[e], AVW(sb + AV_BASE, rb, khi));
                        ldsm4(bL2[e], AVW(sb + AV_BASE, rb, khi + 64));
                    }
#pragma unroll
                    for (int jj = 0; jj < 4; jj++) {
                        int j = gp * 4 + jj;
                        int e = jj >> 1, sub = jj & 1;
                        mma16816(o[j], pH[ks2], &bH2[e][sub * 2]);
                        mma16816(o[j], pH[ks2], &bL2[e][sub * 2]);
                        mma16816(o[j], pL[ks2], &bH2[e][sub * 2]);
                    }
                }
            }
        }

        // ---- finalize: fused hi/lo split into g_AOs ----
        float inv0 = 1.0f / lr0, inv1 = 1.0f / lr1;
        const size_t m0 = (size_t)b * TS + q0;
        const size_t m1 = m0 + 8;
        const int colb = h * DD;
#pragma unroll
        for (int j = 0; j < 16; j++) {
            int col = colb + j * 8 + cb;
            float v0 = o[j][0] * inv0, v1 = o[j][1] * inv0;
            float v2 = o[j][2] * inv1, v3 = o[j][3] * inv1;
            __nv_bfloat16 h0 = __float2bfloat16_rn(v0);
            __nv_bfloat16 h1 = __float2bfloat16_rn(v1);
            __nv_bfloat16 h2 = __float2bfloat16_rn(v2);
            __nv_bfloat16 h3 = __float2bfloat16_rn(v3);
            *(uint32_t*)(g_AOs + m0 * KPA + col)        = bf2u(h0, h1);
            *(uint32_t*)(g_AOs + m1 * KPA + col)        = bf2u(h2, h3);
            *(uint32_t*)(g_AOs + m0 * KPA + 2048 + col) = bf2u(
                __float2bfloat16_rn(v0 - __bfloat162float(h0)),
                __float2bfloat16_rn(v1 - __bfloat162float(h1)));
            *(uint32_t*)(g_AOs + m1 * KPA + 2048 + col) = bf2u(
                __float2bfloat16_rn(v2 - __bfloat162float(h2)),
                __float2bfloat16_rn(v3 - __bfloat162float(h3)));
        }
    }
}

// ---------------------------------------------------------------------------
// Launch
// ---------------------------------------------------------------------------
extern "C" void kernel_launch(void* const* d_in, const int* in_sizes, int n_in,
                              void* d_out, int out_size)
{
    const float* X   = (const float*)d_in[0];
    const float* msk = (const float*)d_in[1];
    const float* Wq  = (const float*)d_in[2];
    const float* Wk  = (const float*)d_in[3];
    const float* Wv  = (const float*)d_in[4];
    const float* Wo  = (const float*)d_in[5];
    float* out = (float*)d_out;

    cudaFuncSetAttribute(attn_kernel, cudaFuncAttributeMaxDynamicSharedMemorySize, ATT_SMEM);
    cudaFuncSetAttribute(tc_gemm_kernel, cudaFuncAttributeMaxDynamicSharedMemorySize, GEMM_SMEM);

    reset_ctr_kernel<<<1, 32>>>();
    cfac_kernel<<<TS, DD>>>();
    splitW_kernel<<<dim3(64, 64, 4), 256>>>(Wq, Wk, Wv, Wo);
    split_kernel<<<8192, 256>>>(X);

    // QKV projections (persistent, work-stealing)
    tc_gemm_kernel<<<296, 256, GEMM_SMEM>>>(0, 1536, 0, nullptr);

    vtrans_kernel<<<dim3(64, 4, 32), 256>>>();

    // attention (persistent, work-stealing)
    attn_kernel<<<296, 256, ATT_SMEM>>>(msk);

    // output projection
    tc_gemm_kernel<<<296, 256, GEMM_SMEM>>>(3, 512, 1, out);
}

// round 10
// speedup vs baseline: 1.0463x; 1.0463x over previous
#include <cuda_runtime.h>
#include <cuda_bf16.h>
#include <math.h>
#include <stdint.h>

// Problem constants
#define BB 2
#define TS 2048
#define HH 16
#define DD 128
#define CC 2048
#define MMR (BB*TS)
#define KPA 4096             // compact split stride: [hi | lo]
#define NCHUNK 96            // logical K' = 3*2048 in 96 chunks of 64

// 1/sqrt(2048)
#define RSQT 0.022097086912079608f

// ---------------------------------------------------------------------------
// Device scratch
// ---------------------------------------------------------------------------
__device__ float g_V [(size_t)BB*HH*TS*DD];          // fp32 V [bh][t][d]
__device__ float g_cfac[TS*DD];
__device__ int   g_ctr[4];
__device__ __nv_bfloat16 g_Qh[(size_t)BB*HH*TS*DD];  // [bh][t][d]
__device__ __nv_bfloat16 g_Ql[(size_t)BB*HH*TS*DD];
__device__ __nv_bfloat16 g_Kh[(size_t)BB*HH*TS*DD];
__device__ __nv_bfloat16 g_Kl[(size_t)BB*HH*TS*DD];
__device__ __nv_bfloat16 g_Vth[(size_t)BB*HH*TS*DD]; // V^T hi [bh][d][t]
__device__ __nv_bfloat16 g_Vtl[(size_t)BB*HH*TS*DD]; // V^T lo
__device__ __nv_bfloat16 g_Xs [(size_t)MMR*KPA];     // [m][4096] : [Xh | Xl]
__device__ __nv_bfloat16 g_AOs[(size_t)MMR*KPA];     // [m][4096] : [AOh | AOl]
__device__ __nv_bfloat16 g_Wt [(size_t)4*CC*KPA];    // [w][n][4096] : [Wh | Wl]

// ---------------------------------------------------------------------------
// PTX helpers (sm_100-baseline-safe)
// ---------------------------------------------------------------------------
__device__ __forceinline__ uint32_t smem_u32(const void* p) {
    uint32_t a;
    asm("{ .reg .u64 t; cvta.to.shared.u64 t, %1; cvt.u32.u64 %0, t; }" : "=r"(a) : "l"(p));
    return a;
}
__device__ __forceinline__ void ldsm4(uint32_t* r, uint32_t addr) {
    asm volatile("ldmatrix.sync.aligned.m8n8.x4.shared.b16 {%0,%1,%2,%3}, [%4];"
        : "=r"(r[0]), "=r"(r[1]), "=r"(r[2]), "=r"(r[3]) : "r"(addr));
}
__device__ __forceinline__ void mma16816(float* d, const uint32_t* a, const uint32_t* b) {
    asm volatile("mma.sync.aligned.m16n8k16.row.col.f32.bf16.bf16.f32 "
        "{%0,%1,%2,%3}, {%4,%5,%6,%7}, {%8,%9}, {%0,%1,%2,%3};"
        : "+f"(d[0]), "+f"(d[1]), "+f"(d[2]), "+f"(d[3])
        : "r"(a[0]), "r"(a[1]), "r"(a[2]), "r"(a[3]), "r"(b[0]), "r"(b[1]));
}
__device__ __forceinline__ void cpa16(uint32_t s, const void* g) {
    asm volatile("cp.async.cg.shared.global [%0], [%1], 16;" :: "r"(s), "l"(g));
}
#define CP_COMMIT() asm volatile("cp.async.commit_group;")
#define CP_WAIT(n)  asm volatile("cp.async.wait_group %0;" :: "n"(n))

__device__ __forceinline__ uint32_t bf2u(__nv_bfloat16 a, __nv_bfloat16 b) {
    __nv_bfloat162 t = __halves2bfloat162(a, b);
    return *(uint32_t*)&t;
}
// swizzled smem address, 256B rows
#define ASW(base, r, kb) ((base) + (uint32_t)(r) * 256 + (((uint32_t)(kb)) ^ ((((uint32_t)(r)) & 7) << 4)))

// ---------------------------------------------------------------------------
// tiny kernels
// ---------------------------------------------------------------------------
__global__ void reset_ctr_kernel() {
    if (threadIdx.x < 4) g_ctr[threadIdx.x] = 0;
}

__global__ void cfac_kernel() {
    int t = blockIdx.x;
    int d = threadIdx.x;
    int j = d & 63;
    float ex = (float)(2 * j) / 128.0f;
    float freq = 1.0f / powf(10000.0f, ex);
    float m = (float)t * freq;
    g_cfac[t * DD + d] = cosf(m) + sinf(m);
}

__global__ __launch_bounds__(256) void split_kernel(const float* __restrict__ xin) {
    int idx = blockIdx.x * 256 + threadIdx.x;
    int m = idx >> 9;
    int kv = (idx & 511) << 2;
    float4 x = *(const float4*)(xin + (size_t)m * CC + kv);
    __nv_bfloat16 h0 = __float2bfloat16_rn(x.x);
    __nv_bfloat16 h1 = __float2bfloat16_rn(x.y);
    __nv_bfloat16 h2 = __float2bfloat16_rn(x.z);
    __nv_bfloat16 h3 = __float2bfloat16_rn(x.w);
    __nv_bfloat16 l0 = __float2bfloat16_rn(x.x - __bfloat162float(h0));
    __nv_bfloat16 l1 = __float2bfloat16_rn(x.y - __bfloat162float(h1));
    __nv_bfloat16 l2 = __float2bfloat16_rn(x.z - __bfloat162float(h2));
    __nv_bfloat16 l3 = __float2bfloat16_rn(x.w - __bfloat162float(h3));
    __nv_bfloat16* p = g_Xs + (size_t)m * KPA + kv;
    *(__nv_bfloat162*)(p)        = __halves2bfloat162(h0, h1);
    *(__nv_bfloat162*)(p + 2)    = __halves2bfloat162(h2, h3);
    *(__nv_bfloat162*)(p + 2048) = __halves2bfloat162(l0, l1);
    *(__nv_bfloat162*)(p + 2050) = __halves2bfloat162(l2, l3);
}

__global__ __launch_bounds__(256) void splitW_kernel(
    const float* __restrict__ Wq, const float* __restrict__ Wk,
    const float* __restrict__ Wv, const float* __restrict__ Wo)
{
    __shared__ float tile[32][33];
    int w = blockIdx.z;
    const float* W = (w == 0) ? Wq : (w == 1) ? Wk : (w == 2) ? Wv : Wo;
    __nv_bfloat16* out = g_Wt + (size_t)w * CC * KPA;
    int n0 = blockIdx.x * 32, k0 = blockIdx.y * 32;
    int tx = threadIdx.x & 31, ty = threadIdx.x >> 5;
#pragma unroll
    for (int r = 0; r < 4; r++) {
        int k = k0 + ty + r * 8;
        tile[ty + r * 8][tx] = W[(size_t)k * CC + n0 + tx];
    }
    __syncthreads();
#pragma unroll
    for (int r = 0; r < 4; r++) {
        int n = n0 + ty + r * 8;
        int k = k0 + tx;
        float x = tile[tx][ty + r * 8];
        __nv_bfloat16 hi = __float2bfloat16_rn(x);
        __nv_bfloat16 lo = __float2bfloat16_rn(x - __bfloat162float(hi));
        __nv_bfloat16* pr = out + (size_t)n * KPA;
        pr[k] = hi; pr[2048 + k] = lo;
    }
}

__global__ __launch_bounds__(256) void vtrans_kernel() {
    __shared__ float tile[32][33];
    int bh = blockIdx.z, t0 = blockIdx.x * 32, d0 = blockIdx.y * 32;
    int tx = threadIdx.x & 31, ty = threadIdx.x >> 5;
    const float* src = g_V + (size_t)bh * TS * DD;
#pragma unroll
    for (int r = 0; r < 4; r++)
        tile[ty + r * 8][tx] = src[(size_t)(t0 + ty + r * 8) * DD + d0 + tx];
    __syncthreads();
#pragma unroll
    for (int r = 0; r < 4; r++) {
        int d = d0 + ty + r * 8;
        int t = t0 + tx;
        float v = tile[tx][ty + r * 8];
        __nv_bfloat16 hv = __float2bfloat16_rn(v);
        __nv_bfloat16 lv = __float2bfloat16_rn(v - __bfloat162float(hv));
        size_t off = (size_t)bh * DD * TS + (size_t)d * TS + t;
        g_Vth[off] = hv;
        g_Vtl[off] = lv;
    }
}

// ---------------------------------------------------------------------------
// mma.sync bf16 GEMM, 3-stage cp.async pipeline, 2 CTAs/SM, work-stealing.
// ---------------------------------------------------------------------------
#define SM_STAGE 32768
#define GEMM_SMEM (1024 + 3 * SM_STAGE)

__global__ __launch_bounds__(256, 2) void tc_gemm_kernel(int modeBase, int ntiles,
                                                         int ci, float* __restrict__ Cout)
{
    extern __shared__ char smc[];
    uint32_t sb = smem_u32(smc) + 1024;
    const int tid = threadIdx.x, wid = tid >> 5, lane = tid & 31;
    const int wm = wid >> 1, wn = wid & 1;

    const int ldrow = tid >> 3;
    const int ldc16 = tid & 7;
    const uint32_t sw = ((uint32_t)(ldrow * 128 + ldc16 * 16)) ^ ((ldrow & 7) << 4);

    const int lh16 = (lane >> 4) * 16;
    const int rowA0 = wm * 32 + (lane & 15);
    const int kbB = ((lane >> 3) & 1) * 16;
    const int rbase = wn * 64 + ((lane >> 4) << 3) + (lane & 7);
    const int rsub = lane >> 2, cb = (lane & 3) * 2;

#define AOFF(k0) ((k0) < 2048 ? (k0) : (k0) - 2048)
#define BOFF(k0) ((k0) < 4096 ? (k0) : (k0) - 4096)

    for (;;) {
        __syncthreads();
        if (tid == 0) ((int*)smc)[0] = atomicAdd(&g_ctr[ci], 1);
        __syncthreads();
        int t = ((int*)smc)[0];
        if (t >= ntiles) { CP_WAIT(0); break; }
        const int mode = modeBase + (t >> 9);
        const int r_ = t & 511;
        const int bm = r_ >> 4, bn = r_ & 15;
        const __nv_bfloat16* A  = (mode == 3) ? g_AOs : g_Xs;
        const __nv_bfloat16* Bp = g_Wt + (size_t)mode * CC * KPA;
        const __nv_bfloat16* Arow = A  + (size_t)(bm * 128) * KPA;
        const __nv_bfloat16* Brow = Bp + (size_t)(bn * 128) * KPA;

        float c[2][8][4];
#pragma unroll
        for (int i = 0; i < 2; i++)
#pragma unroll
            for (int j = 0; j < 8; j++)
#pragma unroll
                for (int q = 0; q < 4; q++) c[i][j][q] = 0.0f;

        // prologue: chunks 0,1 -> stages 0,1
#pragma unroll
        for (int p = 0; p < 2; p++) {
            int k0 = p * 64;
            int ao = AOFF(k0), bo = BOFF(k0);
            uint32_t st = sb + p * SM_STAGE;
#pragma unroll
            for (int it = 0; it < 4; it++) {
                int row = ldrow + it * 32;
                cpa16(st + sw + it * 4096,         Arow + (size_t)row * KPA + ao + ldc16 * 8);
                cpa16(st + 16384 + sw + it * 4096, Brow + (size_t)row * KPA + bo + ldc16 * 8);
            }
            CP_COMMIT();
        }

        int stage = 0;
        for (int ch = 0; ch < NCHUNK; ch++) {
            CP_WAIT(1);
            __syncthreads();
            if (ch + 2 < NCHUNK) {
                int k0 = (ch + 2) * 64;
                int ao = AOFF(k0), bo = BOFF(k0);
                int ns = stage + 2; if (ns >= 3) ns -= 3;
                uint32_t st = sb + ns * SM_STAGE;
#pragma unroll
                for (int it = 0; it < 4; it++) {
                    int row = ldrow + it * 32;
                    cpa16(st + sw + it * 4096,         Arow + (size_t)row * KPA + ao + ldc16 * 8);
                    cpa16(st + 16384 + sw + it * 4096, Brow + (size_t)row * KPA + bo + ldc16 * 8);
                }
            }
            CP_COMMIT();

            uint32_t sbA = sb + stage * SM_STAGE;
            uint32_t sbB = sbA + 16384;
#pragma unroll
            for (int ks = 0; ks < 4; ks++) {
                uint32_t a[2][4], b[4][4];
#pragma unroll
                for (int i = 0; i < 2; i++) {
                    int row = rowA0 + i * 16;
                    uint32_t kb = ks * 32 + lh16;
                    ldsm4(a[i], sbA + row * 128 + (kb ^ ((row & 7) << 4)));
                }
#pragma unroll
                for (int g = 0; g < 4; g++) {
                    int row = rbase + g * 16;
                    uint32_t kb = ks * 32 + kbB;
                    ldsm4(b[g], sbB + row * 128 + (kb ^ ((row & 7) << 4)));
                }
#pragma unroll
                for (int i = 0; i < 2; i++)
#pragma unroll
                    for (int j = 0; j < 8; j++)
                        mma16816(c[i][j], a[i], &b[j >> 1][(j & 1) * 2]);
            }
            if (++stage == 3) stage = 0;
        }

        // epilogue
        const int m0g = bm * 128 + wm * 32;
        const int n0g = bn * 128 + wn * 64;
#pragma unroll
        for (int i = 0; i < 2; i++) {
#pragma unroll
            for (int half = 0; half < 2; half++) {
                int row = m0g + i * 16 + rsub + half * 8;
                if (mode == 3) {
                    float* drow = Cout + (size_t)row * CC;
#pragma unroll
                    for (int j = 0; j < 8; j++) {
                        int col = n0g + j * 8 + cb;
                        *(float2*)(drow + col) = make_float2(c[i][j][half * 2],
                                                             c[i][j][half * 2 + 1]);
                    }
                } else if (mode == 2) {
                    int b = row >> 11, tt = row & 2047;
#pragma unroll
                    for (int j = 0; j < 8; j++) {
                        int col = n0g + j * 8 + cb;
                        int h = col >> 7, d0 = col & 127;
                        float* dst = g_V + ((size_t)(b * HH + h) * TS + tt) * DD + d0;
                        *(float2*)dst = make_float2(c[i][j][half * 2], c[i][j][half * 2 + 1]);
                    }
                } else {
                    int b = row >> 11, tt = row & 2047;
                    __nv_bfloat16* outH = (mode == 0) ? g_Qh : g_Kh;
                    __nv_bfloat16* outL = (mode == 0) ? g_Ql : g_Kl;
                    float s = (mode == 0) ? RSQT : 1.0f;
#pragma unroll
                    for (int j = 0; j < 8; j++) {
                        int col = n0g + j * 8 + cb;
                        int h = col >> 7, d0 = col & 127;
                        float2 f = *(const float2*)(g_cfac + tt * DD + d0);
                        float v0 = c[i][j][half * 2]     * f.x * s;
                        float v1 = c[i][j][half * 2 + 1] * f.y * s;
                        __nv_bfloat16 h0 = __float2bfloat16_rn(v0);
                        __nv_bfloat16 h1 = __float2bfloat16_rn(v1);
                        __nv_bfloat16 l0 = __float2bfloat16_rn(v0 - __bfloat162float(h0));
                        __nv_bfloat16 l1 = __float2bfloat16_rn(v1 - __bfloat162float(h1));
                        size_t off = ((size_t)(b * HH + h) * TS + tt) * DD + d0;
                        *(uint32_t*)(outH + off) = bf2u(h0, h1);
                        *(uint32_t*)(outL + off) = bf2u(l0, l1);
                    }
                }
            }
        }
    }
}

// ---------------------------------------------------------------------------
// Tensor-core flash attention (R7 inner loop: 128-key tiles, 1 CTA/SM),
// persistent work-stealing wrapper. Epilogue writes AO hi/lo planes (fused).
// smem: ctrl(1K) | QH QL (64KB) | KH KL (64KB) | VH VL (64KB)
// ---------------------------------------------------------------------------
#define AQH 1024
#define AQL (AQH + 32768)
#define AKH (AQL + 32768)
#define AKL (AKH + 32768)
#define AVH (AKL + 32768)
#define AVL (AVH + 32768)
#define ATT_SMEM (AVL + 32768)

__global__ __launch_bounds__(256, 1) void attn_kernel(const float* __restrict__ mask)
{
    extern __shared__ char smc[];
    uint32_t sb = smem_u32(smc);
    const int tid = threadIdx.x, wid = tid >> 5, lane = tid & 31;
    const int rsub = lane >> 2, cb = (lane & 3) * 2;
    const int kbB = ((lane >> 3) & 1) * 16;
    const int rbB = (lane & 7) + ((lane >> 4) << 3);
    const int raA = wid * 16 + (lane & 15);
    const uint32_t kbA = (lane >> 4) * 16;

    for (;;) {
        __syncthreads();
        if (tid == 0) ((int*)smc)[0] = atomicAdd(&g_ctr[2], 1);
        __syncthreads();
        int tile = ((int*)smc)[0];
        if (tile >= 512) break;
        const int bh = tile >> 4, mblk = tile & 15;
        const int b = bh >> 4, h = bh & 15;
        const size_t qoff = (size_t)bh * TS * DD + (size_t)mblk * 128 * DD;
        const size_t koff = (size_t)bh * TS * DD;
        const size_t voff = (size_t)bh * DD * TS;
        const int q0 = mblk * 128 + wid * 16 + rsub;

        // Q hi/lo resident load
#pragma unroll
        for (int it = 0; it < 8; it++) {
            int id = it * 256 + tid;
            int r = id >> 4;
            uint32_t kb = (id & 15) * 16;
            cpa16(ASW(sb + AQH, r, kb), (const char*)g_Qh + ((qoff + (size_t)r * DD) << 1) + kb);
            cpa16(ASW(sb + AQL, r, kb), (const char*)g_Ql + ((qoff + (size_t)r * DD) << 1) + kb);
        }
        CP_COMMIT();

        float mr0 = -1e30f, mr1 = -1e30f, lr0 = 0.0f, lr1 = 0.0f;
        float o[16][4];
#pragma unroll
        for (int j = 0; j < 16; j++)
#pragma unroll
            for (int q = 0; q < 4; q++) o[j][q] = 0.0f;

        for (int kt = 0; kt < 16; kt++) {
            __syncthreads();   // previous tile's K/V readers done
#pragma unroll
            for (int it = 0; it < 8; it++) {
                int id = it * 256 + tid;
                int r = id >> 4;
                uint32_t kb = (id & 15) * 16;
                size_t ge = koff + (size_t)(kt * 128 + r) * DD;
                cpa16(ASW(sb + AKH, r, kb), (const char*)g_Kh + (ge << 1) + kb);
                cpa16(ASW(sb + AKL, r, kb), (const char*)g_Kl + (ge << 1) + kb);
            }
            CP_COMMIT();
#pragma unroll
            for (int it = 0; it < 8; it++) {
                int id = it * 256 + tid;
                int r = id >> 4;
                uint32_t kb = (id & 15) * 16;
                size_t ge = voff + (size_t)r * TS + kt * 128;
                cpa16(ASW(sb + AVH, r, kb), (const char*)g_Vth + (ge << 1) + kb);
                cpa16(ASW(sb + AVL, r, kb), (const char*)g_Vtl + (ge << 1) + kb);
            }
            CP_COMMIT();
            CP_WAIT(1);        // Q + K complete (V may fly)
            __syncthreads();

            // ---- S = Qh*Kh + Qh*Kl + Ql*Kh ----
            float s[16][4];
#pragma unroll
            for (int j = 0; j < 16; j++)
#pragma unroll
                for (int q = 0; q < 4; q++) s[j][q] = 0.0f;

#pragma unroll
            for (int ks = 0; ks < 8; ks++) {
                uint32_t aH[4], aL[4], bHf[8][4], bLf[8][4];
                uint32_t kba = ks * 32 + kbA;
                ldsm4(aH, ASW(sb + AQH, raA, kba));
                ldsm4(aL, ASW(sb + AQL, raA, kba));
#pragma unroll
                for (int g = 0; g < 8; g++) {
                    int rb = g * 16 + rbB;
                    uint32_t kb = ks * 32 + kbB;
                    ldsm4(bHf[g], ASW(sb + AKH, rb, kb));
                    ldsm4(bLf[g], ASW(sb + AKL, rb, kb));
                }
#pragma unroll
                for (int j = 0; j < 16; j++) {
                    mma16816(s[j], aH, &bHf[j >> 1][(j & 1) * 2]);
                    mma16816(s[j], aH, &bLf[j >> 1][(j & 1) * 2]);
                    mma16816(s[j], aL, &bHf[j >> 1][(j & 1) * 2]);
                }
            }

            // ---- mask add ----
            const float* mrow0 = mask + ((size_t)b * TS + q0) * TS + (size_t)kt * 128;
            const float* mrow1 = mrow0 + (size_t)8 * TS;
#pragma unroll
            for (int j = 0; j < 16; j++) {
                float2 m0 = *(const float2*)(mrow0 + j * 8 + cb);
                float2 m1 = *(const float2*)(mrow1 + j * 8 + cb);
                s[j][0] += m0.x; s[j][1] += m0.y;
                s[j][2] += m1.x; s[j][3] += m1.y;
            }

            // ---- online softmax ----
            float mt0 = -1e30f, mt1 = -1e30f;
#pragma unroll
            for (int j = 0; j < 16; j++) {
                mt0 = fmaxf(mt0, fmaxf(s[j][0], s[j][1]));
                mt1 = fmaxf(mt1, fmaxf(s[j][2], s[j][3]));
            }
            mt0 = fmaxf(mt0, __shfl_xor_sync(0xffffffffu, mt0, 1));
            mt0 = fmaxf(mt0, __shfl_xor_sync(0xffffffffu, mt0, 2));
            mt1 = fmaxf(mt1, __shfl_xor_sync(0xffffffffu, mt1, 1));
            mt1 = fmaxf(mt1, __shfl_xor_sync(0xffffffffu, mt1, 2));
            float mn0 = fmaxf(mr0, mt0), mn1 = fmaxf(mr1, mt1);
            float al0 = __expf(mr0 - mn0), al1 = __expf(mr1 - mn1);
            mr0 = mn0; mr1 = mn1;
            float rs0 = 0.0f, rs1 = 0.0f;
#pragma unroll
            for (int j = 0; j < 16; j++) {
                s[j][0] = __expf(s[j][0] - mn0); rs0 += s[j][0];
                s[j][1] = __expf(s[j][1] - mn0); rs0 += s[j][1];
                s[j][2] = __expf(s[j][2] - mn1); rs1 += s[j][2];
                s[j][3] = __expf(s[j][3] - mn1); rs1 += s[j][3];
            }
            rs0 += __shfl_xor_sync(0xffffffffu, rs0, 1);
            rs0 += __shfl_xor_sync(0xffffffffu, rs0, 2);
            rs1 += __shfl_xor_sync(0xffffffffu, rs1, 1);
            rs1 += __shfl_xor_sync(0xffffffffu, rs1, 2);
            lr0 = lr0 * al0 + rs0;
            lr1 = lr1 * al1 + rs1;
#pragma unroll
            for (int j = 0; j < 16; j++) {
                o[j][0] *= al0; o[j][1] *= al0;
                o[j][2] *= al1; o[j][3] *= al1;
            }

            CP_WAIT(0);        // V complete
            __syncthreads();

            // ---- O += Ph*Vh + Ph*Vl + Pl*Vh ----
#pragma unroll
            for (int ks = 0; ks < 8; ks++) {
                uint32_t ah[4], alr[4];
#pragma unroll
                for (int half = 0; half < 2; half++) {
                    int j = 2 * ks + half;
                    __nv_bfloat16 h0 = __float2bfloat16_rn(s[j][0]);
                    __nv_bfloat16 h1 = __float2bfloat16_rn(s[j][1]);
                    __nv_bfloat16 h2 = __float2bfloat16_rn(s[j][2]);
                    __nv_bfloat16 h3 = __float2bfloat16_rn(s[j][3]);
                    ah[half * 2 + 0] = bf2u(h0, h1);
                    ah[half * 2 + 1] = bf2u(h2, h3);
                    alr[half * 2 + 0] = bf2u(
                        __float2bfloat16_rn(s[j][0] - __bfloat162float(h0)),
                        __float2bfloat16_rn(s[j][1] - __bfloat162float(h1)));
                    alr[half * 2 + 1] = bf2u(
                        __float2bfloat16_rn(s[j][2] - __bfloat162float(h2)),
                        __float2bfloat16_rn(s[j][3] - __bfloat162float(h3)));
                }
                uint32_t bHf[8][4], bLf[8][4];
#pragma unroll
                for (int g = 0; g < 8; g++) {
                    int rb = g * 16 + rbB;
                    uint32_t kb = ks * 32 + kbB;
                    ldsm4(bHf[g], ASW(sb + AVH, rb, kb));
                    ldsm4(bLf[g], ASW(sb + AVL, rb, kb));
                }
#pragma unroll
                for (int j = 0; j < 16; j++) {
                    mma16816(o[j], ah, &bHf[j >> 1][(j & 1) * 2]);
                    mma16816(o[j], ah, &bLf[j >> 1][(j & 1) * 2]);
                    mma16816(o[j], alr, &bHf[j >> 1][(j & 1) * 2]);
                }
            }
        }

        // ---- finalize: fused hi/lo split into g_AOs ----
        float inv0 = 1.0f / lr0, inv1 = 1.0f / lr1;
        const size_t m0 = (size_t)b * TS + q0;
        const size_t m1 = m0 + 8;
        const int colb = h * DD;
#pragma unroll
        for (int j = 0; j < 16; j++) {
            int col = colb + j * 8 + cb;
            float v0 = o[j][0] * inv0, v1 = o[j][1] * inv0;
            float v2 = o[j][2] * inv1, v3 = o[j][3] * inv1;
            __nv_bfloat16 h0 = __float2bfloat16_rn(v0);
            __nv_bfloat16 h1 = __float2bfloat16_rn(v1);
            __nv_bfloat16 h2 = __float2bfloat16_rn(v2);
            __nv_bfloat16 h3 = __float2bfloat16_rn(v3);
            *(uint32_t*)(g_AOs + m0 * KPA + col)        = bf2u(h0, h1);
            *(uint32_t*)(g_AOs + m1 * KPA + col)        = bf2u(h2, h3);
            *(uint32_t*)(g_AOs + m0 * KPA + 2048 + col) = bf2u(
                __float2bfloat16_rn(v0 - __bfloat162float(h0)),
                __float2bfloat16_rn(v1 - __bfloat162float(h1)));
            *(uint32_t*)(g_AOs + m1 * KPA + 2048 + col) = bf2u(
                __float2bfloat16_rn(v2 - __bfloat162float(h2)),
                __float2bfloat16_rn(v3 - __bfloat162float(h3)));
        }
    }
}

// ---------------------------------------------------------------------------
// Launch
// ---------------------------------------------------------------------------
extern "C" void kernel_launch(void* const* d_in, const int* in_sizes, int n_in,
                              void* d_out, int out_size)
{
    const float* X   = (const float*)d_in[0];
    const float* msk = (const float*)d_in[1];
    const float* Wq  = (const float*)d_in[2];
    const float* Wk  = (const float*)d_in[3];
    const float* Wv  = (const float*)d_in[4];
    const float* Wo  = (const float*)d_in[5];
    float* out = (float*)d_out;

    cudaFuncSetAttribute(attn_kernel, cudaFuncAttributeMaxDynamicSharedMemorySize, ATT_SMEM);
    cudaFuncSetAttribute(tc_gemm_kernel, cudaFuncAttributeMaxDynamicSharedMemorySize, GEMM_SMEM);

    reset_ctr_kernel<<<1, 32>>>();
    cfac_kernel<<<TS, DD>>>();
    splitW_kernel<<<dim3(64, 64, 4), 256>>>(Wq, Wk, Wv, Wo);
    split_kernel<<<8192, 256>>>(X);

    // QKV projections (persistent, work-stealing)
    tc_gemm_kernel<<<296, 256, GEMM_SMEM>>>(0, 1536, 0, nullptr);

    vtrans_kernel<<<dim3(64, 4, 32), 256>>>();

    // attention (persistent, 1 CTA/SM, R7 inner loop)
    attn_kernel<<<148, 256, ATT_SMEM>>>(msk);

    // output projection (persistent, work-stealing)
    tc_gemm_kernel<<<296, 256, GEMM_SMEM>>>(3, 512, 1, out);
}

// round 12
// speedup vs baseline: 1.0775x; 1.0299x over previous
#include <cuda_runtime.h>
#include <cuda_bf16.h>
#include <math.h>
#include <stdint.h>

// Problem constants
#define BB 2
#define TS 2048
#define HH 16
#define DD 128
#define CC 2048
#define MMR (BB*TS)
#define KPA 4096             // compact split stride: [hi | lo]
#define NCHUNK 96            // logical K' = 3*2048 in 96 chunks of 64

// 1/sqrt(2048)
#define RSQT 0.022097086912079608f

// ---------------------------------------------------------------------------
// Device scratch
// ---------------------------------------------------------------------------
__device__ float g_V [(size_t)BB*HH*TS*DD];          // fp32 V [bh][t][d]
__device__ float g_cfac[TS*DD];
__device__ int   g_ctr[4];
__device__ __nv_bfloat16 g_Qh[(size_t)BB*HH*TS*DD];  // [bh][t][d]
__device__ __nv_bfloat16 g_Ql[(size_t)BB*HH*TS*DD];
__device__ __nv_bfloat16 g_Kh[(size_t)BB*HH*TS*DD];
__device__ __nv_bfloat16 g_Kl[(size_t)BB*HH*TS*DD];
__device__ __nv_bfloat16 g_Vth[(size_t)BB*HH*TS*DD]; // V^T hi [bh][d][t]
__device__ __nv_bfloat16 g_Vtl[(size_t)BB*HH*TS*DD]; // V^T lo
__device__ __nv_bfloat16 g_Xs [(size_t)MMR*KPA];     // [m][4096] : [Xh | Xl]
__device__ __nv_bfloat16 g_AOs[(size_t)MMR*KPA];     // [m][4096] : [AOh | AOl]
__device__ __nv_bfloat16 g_Wt [(size_t)4*CC*KPA];    // [w][n][4096] : [Wh | Wl]

// ---------------------------------------------------------------------------
// PTX helpers (sm_100-baseline-safe)
// ---------------------------------------------------------------------------
__device__ __forceinline__ uint32_t smem_u32(const void* p) {
    uint32_t a;
    asm("{ .reg .u64 t; cvta.to.shared.u64 t, %1; cvt.u32.u64 %0, t; }" : "=r"(a) : "l"(p));
    return a;
}
__device__ __forceinline__ void ldsm4(uint32_t* r, uint32_t addr) {
    asm volatile("ldmatrix.sync.aligned.m8n8.x4.shared.b16 {%0,%1,%2,%3}, [%4];"
        : "=r"(r[0]), "=r"(r[1]), "=r"(r[2]), "=r"(r[3]) : "r"(addr));
}
__device__ __forceinline__ void mma16816(float* d, const uint32_t* a, const uint32_t* b) {
    asm volatile("mma.sync.aligned.m16n8k16.row.col.f32.bf16.bf16.f32 "
        "{%0,%1,%2,%3}, {%4,%5,%6,%7}, {%8,%9}, {%0,%1,%2,%3};"
        : "+f"(d[0]), "+f"(d[1]), "+f"(d[2]), "+f"(d[3])
        : "r"(a[0]), "r"(a[1]), "r"(a[2]), "r"(a[3]), "r"(b[0]), "r"(b[1]));
}
__device__ __forceinline__ void cpa16(uint32_t s, const void* g) {
    asm volatile("cp.async.cg.shared.global [%0], [%1], 16;" :: "r"(s), "l"(g));
}
#define CP_COMMIT() asm volatile("cp.async.commit_group;")
#define CP_WAIT(n)  asm volatile("cp.async.wait_group %0;" :: "n"(n))

__device__ __forceinline__ uint32_t bf2u(__nv_bfloat16 a, __nv_bfloat16 b) {
    __nv_bfloat162 t = __halves2bfloat162(a, b);
    return *(uint32_t*)&t;
}
// swizzled smem address, 256B rows
#define ASW(base, r, kb) ((base) + (uint32_t)(r) * 256 + (((uint32_t)(kb)) ^ ((((uint32_t)(r)) & 7) << 4)))

// ---------------------------------------------------------------------------
// tiny kernels
// ---------------------------------------------------------------------------
__global__ void reset_ctr_kernel() {
    if (threadIdx.x < 4) g_ctr[threadIdx.x] = 0;
}

__global__ void cfac_kernel() {
    int t = blockIdx.x;
    int d = threadIdx.x;
    int j = d & 63;
    float ex = (float)(2 * j) / 128.0f;
    float freq = 1.0f / powf(10000.0f, ex);
    float m = (float)t * freq;
    g_cfac[t * DD + d] = cosf(m) + sinf(m);
}

__global__ __launch_bounds__(256) void split_kernel(const float* __restrict__ xin) {
    int idx = blockIdx.x * 256 + threadIdx.x;
    int m = idx >> 9;
    int kv = (idx & 511) << 2;
    float4 x = *(const float4*)(xin + (size_t)m * CC + kv);
    __nv_bfloat16 h0 = __float2bfloat16_rn(x.x);
    __nv_bfloat16 h1 = __float2bfloat16_rn(x.y);
    __nv_bfloat16 h2 = __float2bfloat16_rn(x.z);
    __nv_bfloat16 h3 = __float2bfloat16_rn(x.w);
    __nv_bfloat16 l0 = __float2bfloat16_rn(x.x - __bfloat162float(h0));
    __nv_bfloat16 l1 = __float2bfloat16_rn(x.y - __bfloat162float(h1));
    __nv_bfloat16 l2 = __float2bfloat16_rn(x.z - __bfloat162float(h2));
    __nv_bfloat16 l3 = __float2bfloat16_rn(x.w - __bfloat162float(h3));
    __nv_bfloat16* p = g_Xs + (size_t)m * KPA + kv;
    *(__nv_bfloat162*)(p)        = __halves2bfloat162(h0, h1);
    *(__nv_bfloat162*)(p + 2)    = __halves2bfloat162(h2, h3);
    *(__nv_bfloat162*)(p + 2048) = __halves2bfloat162(l0, l1);
    *(__nv_bfloat162*)(p + 2050) = __halves2bfloat162(l2, l3);
}

__global__ __launch_bounds__(256) void splitW_kernel(
    const float* __restrict__ Wq, const float* __restrict__ Wk,
    const float* __restrict__ Wv, const float* __restrict__ Wo)
{
    __shared__ float tile[32][33];
    int w = blockIdx.z;
    const float* W = (w == 0) ? Wq : (w == 1) ? Wk : (w == 2) ? Wv : Wo;
    __nv_bfloat16* out = g_Wt + (size_t)w * CC * KPA;
    int n0 = blockIdx.x * 32, k0 = blockIdx.y * 32;
    int tx = threadIdx.x & 31, ty = threadIdx.x >> 5;
#pragma unroll
    for (int r = 0; r < 4; r++) {
        int k = k0 + ty + r * 8;
        tile[ty + r * 8][tx] = W[(size_t)k * CC + n0 + tx];
    }
    __syncthreads();
#pragma unroll
    for (int r = 0; r < 4; r++) {
        int n = n0 + ty + r * 8;
        int k = k0 + tx;
        float x = tile[tx][ty + r * 8];
        __nv_bfloat16 hi = __float2bfloat16_rn(x);
        __nv_bfloat16 lo = __float2bfloat16_rn(x - __bfloat162float(hi));
        __nv_bfloat16* pr = out + (size_t)n * KPA;
        pr[k] = hi; pr[2048 + k] = lo;
    }
}

__global__ __launch_bounds__(256) void vtrans_kernel() {
    __shared__ float tile[32][33];
    int bh = blockIdx.z, t0 = blockIdx.x * 32, d0 = blockIdx.y * 32;
    int tx = threadIdx.x & 31, ty = threadIdx.x >> 5;
    const float* src = g_V + (size_t)bh * TS * DD;
#pragma unroll
    for (int r = 0; r < 4; r++)
        tile[ty + r * 8][tx] = src[(size_t)(t0 + ty + r * 8) * DD + d0 + tx];
    __syncthreads();
#pragma unroll
    for (int r = 0; r < 4; r++) {
        int d = d0 + ty + r * 8;
        int t = t0 + tx;
        float v = tile[tx][ty + r * 8];
        __nv_bfloat16 hv = __float2bfloat16_rn(v);
        __nv_bfloat16 lv = __float2bfloat16_rn(v - __bfloat162float(hv));
        size_t off = (size_t)bh * DD * TS + (size_t)d * TS + t;
        g_Vth[off] = hv;
        g_Vtl[off] = lv;
    }
}

// ---------------------------------------------------------------------------
// mma.sync bf16 GEMM: 128 threads/CTA, 4 warps of 64x64 tiles (2m x 2n),
// 3-stage cp.async pipeline, 2 CTAs/SM, work-stealing.
// Issue-density optimized: 8 LDSM per 32 MMA (vs 6 per 16 in the old shape).
// ---------------------------------------------------------------------------
#define SM_STAGE 32768                 // A 16KB + B 16KB
#define GEMM_SMEM (1024 + 3 * SM_STAGE)

__global__ __launch_bounds__(128, 2) void tc_gemm_kernel(int modeBase, int ntiles,
                                                         int ci, float* __restrict__ Cout)
{
    extern __shared__ char smc[];
    uint32_t sb = smem_u32(smc) + 1024;
    const int tid = threadIdx.x, wid = tid >> 5, lane = tid & 31;
    const int wm = wid >> 1, wn = wid & 1;          // 2 x 2 warp grid, 64x64 each

    const int ldrow = tid >> 3;                     // 0..15 (+16 per pass)
    const int ldc16 = tid & 7;
    const uint32_t sw = ((uint32_t)(ldrow * 128 + ldc16 * 16)) ^ ((ldrow & 7) << 4);

    const int lh16 = (lane >> 4) * 16;
    const int rowA0 = wm * 64 + (lane & 15);
    const int kbB = ((lane >> 3) & 1) * 16;
    const int rbase = wn * 64 + ((lane >> 4) << 3) + (lane & 7);
    const int rsub = lane >> 2, cb = (lane & 3) * 2;

#define AOFF(k0) ((k0) < 2048 ? (k0) : (k0) - 2048)
#define BOFF(k0) ((k0) < 4096 ? (k0) : (k0) - 4096)

    for (;;) {
        __syncthreads();
        if (tid == 0) ((int*)smc)[0] = atomicAdd(&g_ctr[ci], 1);
        __syncthreads();
        int t = ((int*)smc)[0];
        if (t >= ntiles) { CP_WAIT(0); break; }
        const int mode = modeBase + (t >> 9);
        const int r_ = t & 511;
        const int bm = r_ >> 4, bn = r_ & 15;
        const __nv_bfloat16* A  = (mode == 3) ? g_AOs : g_Xs;
        const __nv_bfloat16* Bp = g_Wt + (size_t)mode * CC * KPA;
        const __nv_bfloat16* Arow = A  + (size_t)(bm * 128) * KPA;
        const __nv_bfloat16* Brow = Bp + (size_t)(bn * 128) * KPA;

        float c[4][8][4];
#pragma unroll
        for (int i = 0; i < 4; i++)
#pragma unroll
            for (int j = 0; j < 8; j++)
#pragma unroll
                for (int q = 0; q < 4; q++) c[i][j][q] = 0.0f;

        // prologue: chunks 0,1 -> stages 0,1
#pragma unroll
        for (int p = 0; p < 2; p++) {
            int k0 = p * 64;
            int ao = AOFF(k0), bo = BOFF(k0);
            uint32_t st = sb + p * SM_STAGE;
#pragma unroll
            for (int pass = 0; pass < 8; pass++) {
                int row = ldrow + pass * 16;
                cpa16(st + sw + pass * 2048,         Arow + (size_t)row * KPA + ao + ldc16 * 8);
                cpa16(st + 16384 + sw + pass * 2048, Brow + (size_t)row * KPA + bo + ldc16 * 8);
            }
            CP_COMMIT();
        }

        int stage = 0;
        for (int ch = 0; ch < NCHUNK; ch++) {
            CP_WAIT(1);
            __syncthreads();
            if (ch + 2 < NCHUNK) {
                int k0 = (ch + 2) * 64;
                int ao = AOFF(k0), bo = BOFF(k0);
                int ns = stage + 2; if (ns >= 3) ns -= 3;
                uint32_t st = sb + ns * SM_STAGE;
#pragma unroll
                for (int pass = 0; pass < 8; pass++) {
                    int row = ldrow + pass * 16;
                    cpa16(st + sw + pass * 2048,         Arow + (size_t)row * KPA + ao + ldc16 * 8);
                    cpa16(st + 16384 + sw + pass * 2048, Brow + (size_t)row * KPA + bo + ldc16 * 8);
                }
            }
            CP_COMMIT();

            uint32_t sbA = sb + stage * SM_STAGE;
            uint32_t sbB = sbA + 16384;
#pragma unroll
            for (int ks = 0; ks < 4; ks++) {
                uint32_t a[4][4], b[4][4];
#pragma unroll
                for (int i = 0; i < 4; i++) {
                    int row = rowA0 + i * 16;
                    uint32_t kb = ks * 32 + lh16;
                    ldsm4(a[i], sbA + row * 128 + (kb ^ ((row & 7) << 4)));
                }
#pragma unroll
                for (int g = 0; g < 4; g++) {
                    int row = rbase + g * 16;
                    uint32_t kb = ks * 32 + kbB;
                    ldsm4(b[g], sbB + row * 128 + (kb ^ ((row & 7) << 4)));
                }
#pragma unroll
                for (int i = 0; i < 4; i++)
#pragma unroll
                    for (int j = 0; j < 8; j++)
                        mma16816(c[i][j], a[i], &b[j >> 1][(j & 1) * 2]);
            }
            if (++stage == 3) stage = 0;
        }

        // epilogue
        const int m0g = bm * 128 + wm * 64;
        const int n0g = bn * 128 + wn * 64;
#pragma unroll
        for (int i = 0; i < 4; i++) {
#pragma unroll
            for (int half = 0; half < 2; half++) {
                int row = m0g + i * 16 + rsub + half * 8;
                if (mode == 3) {
                    float* drow = Cout + (size_t)row * CC;
#pragma unroll
                    for (int j = 0; j < 8; j++) {
                        int col = n0g + j * 8 + cb;
                        *(float2*)(drow + col) = make_float2(c[i][j][half * 2],
                                                             c[i][j][half * 2 + 1]);
                    }
                } else if (mode == 2) {
                    int b = row >> 11, tt = row & 2047;
#pragma unroll
                    for (int j = 0; j < 8; j++) {
                        int col = n0g + j * 8 + cb;
                        int h = col >> 7, d0 = col & 127;
                        float* dst = g_V + ((size_t)(b * HH + h) * TS + tt) * DD + d0;
                        *(float2*)dst = make_float2(c[i][j][half * 2], c[i][j][half * 2 + 1]);
                    }
                } else {
                    int b = row >> 11, tt = row & 2047;
                    __nv_bfloat16* outH = (mode == 0) ? g_Qh : g_Kh;
                    __nv_bfloat16* outL = (mode == 0) ? g_Ql : g_Kl;
                    float s = (mode == 0) ? RSQT : 1.0f;
#pragma unroll
                    for (int j = 0; j < 8; j++) {
                        int col = n0g + j * 8 + cb;
                        int h = col >> 7, d0 = col & 127;
                        float2 f = *(const float2*)(g_cfac + tt * DD + d0);
                        float v0 = c[i][j][half * 2]     * f.x * s;
                        float v1 = c[i][j][half * 2 + 1] * f.y * s;
                        __nv_bfloat16 h0 = __float2bfloat16_rn(v0);
                        __nv_bfloat16 h1 = __float2bfloat16_rn(v1);
                        __nv_bfloat16 l0 = __float2bfloat16_rn(v0 - __bfloat162float(h0));
                        __nv_bfloat16 l1 = __float2bfloat16_rn(v1 - __bfloat162float(h1));
                        size_t off = ((size_t)(b * HH + h) * TS + tt) * DD + d0;
                        *(uint32_t*)(outH + off) = bf2u(h0, h1);
                        *(uint32_t*)(outL + off) = bf2u(l0, l1);
                    }
                }
            }
        }
    }
}

// ---------------------------------------------------------------------------
// Tensor-core flash attention (128-key tiles, 1 CTA/SM), persistent
// work-stealing wrapper. Epilogue writes AO hi/lo planes (fused split).
// smem: ctrl(1K) | QH QL (64KB) | KH KL (64KB) | VH VL (64KB)
// ---------------------------------------------------------------------------
#define AQH 1024
#define AQL (AQH + 32768)
#define AKH (AQL + 32768)
#define AKL (AKH + 32768)
#define AVH (AKL + 32768)
#define AVL (AVH + 32768)
#define ATT_SMEM (AVL + 32768)

__global__ __launch_bounds__(256, 1) void attn_kernel(const float* __restrict__ mask)
{
    extern __shared__ char smc[];
    uint32_t sb = smem_u32(smc);
    const int tid = threadIdx.x, wid = tid >> 5, lane = tid & 31;
    const int rsub = lane >> 2, cb = (lane & 3) * 2;
    const int kbB = ((lane >> 3) & 1) * 16;
    const int rbB = (lane & 7) + ((lane >> 4) << 3);
    const int raA = wid * 16 + (lane & 15);
    const uint32_t kbA = (lane >> 4) * 16;

    for (;;) {
        __syncthreads();
        if (tid == 0) ((int*)smc)[0] = atomicAdd(&g_ctr[2], 1);
        __syncthreads();
        int tile = ((int*)smc)[0];
        if (tile >= 512) break;
        const int bh = tile >> 4, mblk = tile & 15;
        const int b = bh >> 4, h = bh & 15;
        const size_t qoff = (size_t)bh * TS * DD + (size_t)mblk * 128 * DD;
        const size_t koff = (size_t)bh * TS * DD;
        const size_t voff = (size_t)bh * DD * TS;
        const int q0 = mblk * 128 + wid * 16 + rsub;

        // Q hi/lo resident load
#pragma unroll
        for (int it = 0; it < 8; it++) {
            int id = it * 256 + tid;
            int r = id >> 4;
            uint32_t kb = (id & 15) * 16;
            cpa16(ASW(sb + AQH, r, kb), (const char*)g_Qh + ((qoff + (size_t)r * DD) << 1) + kb);
            cpa16(ASW(sb + AQL, r, kb), (const char*)g_Ql + ((qoff + (size_t)r * DD) << 1) + kb);
        }
        CP_COMMIT();

        float mr0 = -1e30f, mr1 = -1e30f, lr0 = 0.0f, lr1 = 0.0f;
        float o[16][4];
#pragma unroll
        for (int j = 0; j < 16; j++)
#pragma unroll
            for (int q = 0; q < 4; q++) o[j][q] = 0.0f;

        for (int kt = 0; kt < 16; kt++) {
            __syncthreads();   // previous tile's K/V readers done
#pragma unroll
            for (int it = 0; it < 8; it++) {
                int id = it * 256 + tid;
                int r = id >> 4;
                uint32_t kb = (id & 15) * 16;
                size_t ge = koff + (size_t)(kt * 128 + r) * DD;
                cpa16(ASW(sb + AKH, r, kb), (const char*)g_Kh + (ge << 1) + kb);
                cpa16(ASW(sb + AKL, r, kb), (const char*)g_Kl + (ge << 1) + kb);
            }
            CP_COMMIT();
#pragma unroll
            for (int it = 0; it < 8; it++) {
                int id = it * 256 + tid;
                int r = id >> 4;
                uint32_t kb = (id & 15) * 16;
                size_t ge = voff + (size_t)r * TS + kt * 128;
                cpa16(ASW(sb + AVH, r, kb), (const char*)g_Vth + (ge << 1) + kb);
                cpa16(ASW(sb + AVL, r, kb), (const char*)g_Vtl + (ge << 1) + kb);
            }
            CP_COMMIT();
            CP_WAIT(1);        // Q + K complete (V may fly)
            __syncthreads();

            // ---- S = Qh*Kh + Qh*Kl + Ql*Kh ----
            float s[16][4];
#pragma unroll
            for (int j = 0; j < 16; j++)
#pragma unroll
                for (int q = 0; q < 4; q++) s[j][q] = 0.0f;

#pragma unroll
            for (int ks = 0; ks < 8; ks++) {
                uint32_t aH[4], aL[4], bHf[8][4], bLf[8][4];
                uint32_t kba = ks * 32 + kbA;
                ldsm4(aH, ASW(sb + AQH, raA, kba));
                ldsm4(aL, ASW(sb + AQL, raA, kba));
#pragma unroll
                for (int g = 0; g < 8; g++) {
                    int rb = g * 16 + rbB;
                    uint32_t kb = ks * 32 + kbB;
                    ldsm4(bHf[g], ASW(sb + AKH, rb, kb));
                    ldsm4(bLf[g], ASW(sb + AKL, rb, kb));
                }
#pragma unroll
                for (int j = 0; j < 16; j++) {
                    mma16816(s[j], aH, &bHf[j >> 1][(j & 1) * 2]);
                    mma16816(s[j], aH, &bLf[j >> 1][(j & 1) * 2]);
                    mma16816(s[j], aL, &bHf[j >> 1][(j & 1) * 2]);
                }
            }

            // ---- mask add ----
            const float* mrow0 = mask + ((size_t)b * TS + q0) * TS + (size_t)kt * 128;
            const float* mrow1 = mrow0 + (size_t)8 * TS;
#pragma unroll
            for (int j = 0; j < 16; j++) {
                float2 m0 = *(const float2*)(mrow0 + j * 8 + cb);
                float2 m1 = *(const float2*)(mrow1 + j * 8 + cb);
                s[j][0] += m0.x; s[j][1] += m0.y;
                s[j][2] += m1.x; s[j][3] += m1.y;
            }

            // ---- online softmax ----
            float mt0 = -1e30f, mt1 = -1e30f;
#pragma unroll
            for (int j = 0; j < 16; j++) {
                mt0 = fmaxf(mt0, fmaxf(s[j][0], s[j][1]));
                mt1 = fmaxf(mt1, fmaxf(s[j][2], s[j][3]));
            }
            mt0 = fmaxf(mt0, __shfl_xor_sync(0xffffffffu, mt0, 1));
            mt0 = fmaxf(mt0, __shfl_xor_sync(0xffffffffu, mt0, 2));
            mt1 = fmaxf(mt1, __shfl_xor_sync(0xffffffffu, mt1, 1));
            mt1 = fmaxf(mt1, __shfl_xor_sync(0xffffffffu, mt1, 2));
            float mn0 = fmaxf(mr0, mt0), mn1 = fmaxf(mr1, mt1);
            float al0 = __expf(mr0 - mn0), al1 = __expf(mr1 - mn1);
            mr0 = mn0; mr1 = mn1;
            float rs0 = 0.0f, rs1 = 0.0f;
#pragma unroll
            for (int j = 0; j < 16; j++) {
                s[j][0] = __expf(s[j][0] - mn0); rs0 += s[j][0];
                s[j][1] = __expf(s[j][1] - mn0); rs0 += s[j][1];
                s[j][2] = __expf(s[j][2] - mn1); rs1 += s[j][2];
                s[j][3] = __expf(s[j][3] - mn1); rs1 += s[j][3];
            }
            rs0 += __shfl_xor_sync(0xffffffffu, rs0, 1);
            rs0 += __shfl_xor_sync(0xffffffffu, rs0, 2);
            rs1 += __shfl_xor_sync(0xffffffffu, rs1, 1);
            rs1 += __shfl_xor_sync(0xffffffffu, rs1, 2);
            lr0 = lr0 * al0 + rs0;
            lr1 = lr1 * al1 + rs1;
#pragma unroll
            for (int j = 0; j < 16; j++) {
                o[j][0] *= al0; o[j][1] *= al0;
                o[j][2] *= al1; o[j][3] *= al1;
            }

            CP_WAIT(0);        // V complete
            __syncthreads();

            // ---- O += Ph*Vh + Ph*Vl + Pl*Vh ----
#pragma unroll
            for (int ks = 0; ks < 8; ks++) {
                uint32_t ah[4], alr[4];
#pragma unroll
                for (int half = 0; half < 2; half++) {
                    int j = 2 * ks + half;
                    __nv_bfloat16 h0 = __float2bfloat16_rn(s[j][0]);
                    __nv_bfloat16 h1 = __float2bfloat16_rn(s[j][1]);
                    __nv_bfloat16 h2 = __float2bfloat16_rn(s[j][2]);
                    __nv_bfloat16 h3 = __float2bfloat16_rn(s[j][3]);
                    ah[half * 2 + 0] = bf2u(h0, h1);
                    ah[half * 2 + 1] = bf2u(h2, h3);
                    alr[half * 2 + 0] = bf2u(
                        __float2bfloat16_rn(s[j][0] - __bfloat162float(h0)),
                        __float2bfloat16_rn(s[j][1] - __bfloat162float(h1)));
                    alr[half * 2 + 1] = bf2u(
                        __float2bfloat16_rn(s[j][2] - __bfloat162float(h2)),
                        __float2bfloat16_rn(s[j][3] - __bfloat162float(h3)));
                }
                uint32_t bHf[8][4], bLf[8][4];
#pragma unroll
                for (int g = 0; g < 8; g++) {
                    int rb = g * 16 + rbB;
                    uint32_t kb = ks * 32 + kbB;
                    ldsm4(bHf[g], ASW(sb + AVH, rb, kb));
                    ldsm4(bLf[g], ASW(sb + AVL, rb, kb));
                }
#pragma unroll
                for (int j = 0; j < 16; j++) {
                    mma16816(o[j], ah, &bHf[j >> 1][(j & 1) * 2]);
                    mma16816(o[j], ah, &bLf[j >> 1][(j & 1) * 2]);
                    mma16816(o[j], alr, &bHf[j >> 1][(j & 1) * 2]);
                }
            }
        }

        // ---- finalize: fused hi/lo split into g_AOs ----
        float inv0 = 1.0f / lr0, inv1 = 1.0f / lr1;
        const size_t m0 = (size_t)b * TS + q0;
        const size_t m1 = m0 + 8;
        const int colb = h * DD;
#pragma unroll
        for (int j = 0; j < 16; j++) {
            int col = colb + j * 8 + cb;
            float v0 = o[j][0] * inv0, v1 = o[j][1] * inv0;
            float v2 = o[j][2] * inv1, v3 = o[j][3] * inv1;
            __nv_bfloat16 h0 = __float2bfloat16_rn(v0);
            __nv_bfloat16 h1 = __float2bfloat16_rn(v1);
            __nv_bfloat16 h2 = __float2bfloat16_rn(v2);
            __nv_bfloat16 h3 = __float2bfloat16_rn(v3);
            *(uint32_t*)(g_AOs + m0 * KPA + col)        = bf2u(h0, h1);
            *(uint32_t*)(g_AOs + m1 * KPA + col)        = bf2u(h2, h3);
            *(uint32_t*)(g_AOs + m0 * KPA + 2048 + col) = bf2u(
                __float2bfloat16_rn(v0 - __bfloat162float(h0)),
                __float2bfloat16_rn(v1 - __bfloat162float(h1)));
            *(uint32_t*)(g_AOs + m1 * KPA + 2048 + col) = bf2u(
                __float2bfloat16_rn(v2 - __bfloat162float(h2)),
                __float2bfloat16_rn(v3 - __bfloat162float(h3)));
        }
    }
}

// ---------------------------------------------------------------------------
// Launch
// ---------------------------------------------------------------------------
extern "C" void kernel_launch(void* const* d_in, const int* in_sizes, int n_in,
                              void* d_out, int out_size)
{
    const float* X   = (const float*)d_in[0];
    const float* msk = (const float*)d_in[1];
    const float* Wq  = (const float*)d_in[2];
    const float* Wk  = (const float*)d_in[3];
    const float* Wv  = (const float*)d_in[4];
    const float* Wo  = (const float*)d_in[5];
    float* out = (float*)d_out;

    cudaFuncSetAttribute(attn_kernel, cudaFuncAttributeMaxDynamicSharedMemorySize, ATT_SMEM);
    cudaFuncSetAttribute(tc_gemm_kernel, cudaFuncAttributeMaxDynamicSharedMemorySize, GEMM_SMEM);

    reset_ctr_kernel<<<1, 32>>>();
    cfac_kernel<<<TS, DD>>>();
    splitW_kernel<<<dim3(64, 64, 4), 256>>>(Wq, Wk, Wv, Wo);
    split_kernel<<<8192, 256>>>(X);

    // QKV projections (persistent, work-stealing, 64x64 warp tiles)
    tc_gemm_kernel<<<296, 128, GEMM_SMEM>>>(0, 1536, 0, nullptr);

    vtrans_kernel<<<dim3(64, 4, 32), 256>>>();

    // attention (persistent, 1 CTA/SM)
    attn_kernel<<<148, 256, ATT_SMEM>>>(msk);

    // output projection (persistent, work-stealing)
    tc_gemm_kernel<<<296, 128, GEMM_SMEM>>>(3, 512, 1, out);
}